// round 1
// baseline (speedup 1.0000x reference)
#include <cuda_runtime.h>
#include <cuda_bf16.h>

// Problem constants
#define B_ 1024
#define T_ 256
#define V_ 50000
#define E_ 512
#define U_ 1024

// GEMM tiling
#define BM 128
#define BN 64
#define BK 16
#define ASTRIDE (BM + 4)   // 132: keeps 16B alignment for LDS.128, reduces STS conflicts
#define NBLK 128           // persistent grid: (1024/BM) * (1024/BN) = 8*16

// Scratch (device globals: allocation-free per harness rules)
__device__ float g_EW0[(size_t)V_ * U_];       // 204.8 MB: emb @ W0, gathered per step
__device__ float g_H0[2 * B_ * U_];            // ping-pong hidden state layer 0
__device__ float g_H1[2 * B_ * U_];            // ping-pong hidden state layer 1
__device__ unsigned g_bar_count = 0;
__device__ volatile unsigned g_bar_gen = 0;

// ---------------------------------------------------------------------------
// Grid-wide barrier (128 resident CTAs). Release via gen counter; count reset
// by releaser. threadfence publishes H writes (stores are .cg -> L2 anyway).
// ---------------------------------------------------------------------------
__device__ __forceinline__ void grid_sync() {
    __syncthreads();
    if (threadIdx.x == 0) {
        __threadfence();
        unsigned g = g_bar_gen;
        unsigned a = atomicAdd(&g_bar_count, 1);
        if (a == NBLK - 1) {
            g_bar_count = 0;
            __threadfence();
            g_bar_gen = g + 1;
        } else {
            while (g_bar_gen == g) { __nanosleep(32); }
        }
        __threadfence();
    }
    __syncthreads();
}

// ---------------------------------------------------------------------------
// Shared SGEMM mainloop: C_tile(128x64) += A[rows,K] * B[K,cols]
// 256 threads, 8x4 per thread, double-buffered smem.
// ACG=true -> A loaded with .cg (mutable H state; L1 is stale across SMs).
// ---------------------------------------------------------------------------
__device__ __forceinline__ float4 ld4_cg(const float* p) { return __ldcg((const float4*)p); }
__device__ __forceinline__ float4 ld4_ro(const float* p) { return __ldg((const float4*)p); }

template <bool ACG>
__device__ __forceinline__ void gt_loadA(float4 aR[2], const float* A, int lda,
                                         int rowBase, int kBase, int maxRow, int tid) {
#pragma unroll
    for (int j = 0; j < 2; j++) {
        int i = tid + (j << 8);
        int arow = i >> 2;
        int acol = (i & 3) << 2;
        int r = rowBase + arow;
        if (r > maxRow) r = maxRow;
        const float* p = A + (size_t)r * lda + kBase + acol;
        aR[j] = ACG ? ld4_cg(p) : ld4_ro(p);
    }
}

__device__ __forceinline__ void gt_storeA(const float4 aR[2], float* AsBuf, int tid) {
#pragma unroll
    for (int j = 0; j < 2; j++) {
        int i = tid + (j << 8);
        int arow = i >> 2;
        int acol = (i & 3) << 2;
        AsBuf[(acol + 0) * ASTRIDE + arow] = aR[j].x;
        AsBuf[(acol + 1) * ASTRIDE + arow] = aR[j].y;
        AsBuf[(acol + 2) * ASTRIDE + arow] = aR[j].z;
        AsBuf[(acol + 3) * ASTRIDE + arow] = aR[j].w;
    }
}

__device__ __forceinline__ void gt_loadB(float4& bR, const float* Bm, int ldb,
                                         int colBase, int kBase, int tid) {
    int brow = tid >> 4;
    int bcol = (tid & 15) << 2;
    bR = ld4_ro(Bm + (size_t)(kBase + brow) * ldb + colBase + bcol);
}

__device__ __forceinline__ void gt_storeB(const float4 bR, float* BsBuf, int tid) {
    int brow = tid >> 4;
    int bcol = (tid & 15) << 2;
    *(float4*)(BsBuf + brow * BN + bcol) = bR;
}

template <bool ACG>
__device__ __forceinline__ void gemm_tile(const float* __restrict__ A, int lda, int maxRow,
                                          const float* __restrict__ Bm, int ldb, int K,
                                          int rowBase, int colBase,
                                          float* AsS, float* BsS,
                                          float acc[8][4], int tid) {
    const int ABUF = BK * ASTRIDE;
    const int BBUF = BK * BN;
    const int tx = tid & 15;
    const int ty = tid >> 4;

    float4 aR[2];
    float4 bR;
    gt_loadA<ACG>(aR, A, lda, rowBase, 0, maxRow, tid);
    gt_loadB(bR, Bm, ldb, colBase, 0, tid);
    gt_storeA(aR, AsS, tid);
    gt_storeB(bR, BsS, tid);
    __syncthreads();

    const int nC = K >> 4;
#pragma unroll 2
    for (int c = 0; c < nC; c++) {
        const int cur = c & 1;
        if (c + 1 < nC) {
            gt_loadA<ACG>(aR, A, lda, rowBase, (c + 1) << 4, maxRow, tid);
            gt_loadB(bR, Bm, ldb, colBase, (c + 1) << 4, tid);
        }
        const float* As = AsS + cur * ABUF;
        const float* Bs = BsS + cur * BBUF;
#pragma unroll 8
        for (int k = 0; k < BK; k++) {
            float4 a0 = *(const float4*)(As + k * ASTRIDE + (ty << 3));
            float4 a1 = *(const float4*)(As + k * ASTRIDE + (ty << 3) + 4);
            float4 bv = *(const float4*)(Bs + k * BN + (tx << 2));
            float av[8] = {a0.x, a0.y, a0.z, a0.w, a1.x, a1.y, a1.z, a1.w};
            float bw[4] = {bv.x, bv.y, bv.z, bv.w};
#pragma unroll
            for (int i = 0; i < 8; i++)
#pragma unroll
                for (int j = 0; j < 4; j++)
                    acc[i][j] = fmaf(av[i], bw[j], acc[i][j]);
        }
        if (c + 1 < nC) {
            gt_storeA(aR, AsS + (cur ^ 1) * ABUF, tid);
            gt_storeB(bR, BsS + (cur ^ 1) * BBUF, tid);
        }
        __syncthreads();
    }
}

// ---------------------------------------------------------------------------
// Phase 1: EW0[V,U] = emb[V,E] @ W0[E,U]   (52 GF, embarrassingly parallel)
// ---------------------------------------------------------------------------
__global__ void __launch_bounds__(256) k_ew0(const float* __restrict__ emb,
                                             const float* __restrict__ W0) {
    __shared__ float AsS[2 * BK * ASTRIDE];
    __shared__ float BsS[2 * BK * BN];
    const int tid = threadIdx.x;
    const int tx = tid & 15;
    const int ty = tid >> 4;
    const int rowBase = blockIdx.x << 7;
    const int colBase = blockIdx.y << 6;

    float acc[8][4];
#pragma unroll
    for (int i = 0; i < 8; i++)
#pragma unroll
        for (int j = 0; j < 4; j++) acc[i][j] = 0.f;

    gemm_tile<false>(emb, E_, V_ - 1, W0, U_, E_, rowBase, colBase, AsS, BsS, acc, tid);

#pragma unroll
    for (int i = 0; i < 8; i++) {
        int r = rowBase + (ty << 3) + i;
        if (r < V_) {
            float4 o = make_float4(acc[i][0], acc[i][1], acc[i][2], acc[i][3]);
            *(float4*)(g_EW0 + (size_t)r * U_ + colBase + (tx << 2)) = o;
        }
    }
}

// ---------------------------------------------------------------------------
// Phase 2: persistent RNN. 128 CTAs; each owns one 128x64 tile of H.
// Per step:  H0c = tanh(EW0[idx] + H0p@U0 + b0)   -> sync
//            H1c = tanh(H0c@W1 + H1p@U1 + b1)     -> sync
// ---------------------------------------------------------------------------
__global__ void __launch_bounds__(256, 1) k_rnn_persistent(
    const int* __restrict__ inputs,
    const float* __restrict__ U0, const float* __restrict__ b0,
    const float* __restrict__ W1, const float* __restrict__ U1,
    const float* __restrict__ b1) {
    __shared__ float AsS[2 * BK * ASTRIDE];
    __shared__ float BsS[2 * BK * BN];
    const int tid = threadIdx.x;
    const int bid = blockIdx.x;
    const int tx = tid & 15;
    const int ty = tid >> 4;
    const int rowBase = (bid >> 4) << 7;  // 8 row tiles of 128
    const int colBase = (bid & 15) << 6;  // 16 col tiles of 64

    // Zero-init parity-0 state buffers (read at t=0). .cg stores -> L2 visible.
    {
        float4 z = make_float4(0.f, 0.f, 0.f, 0.f);
        float4* h0 = (float4*)g_H0;
        float4* h1 = (float4*)g_H1;
        for (int i = (bid << 8) + tid; i < (B_ * U_ / 4); i += NBLK * 256) {
            __stcg(h0 + i, z);
            __stcg(h1 + i, z);
        }
    }
    grid_sync();

    const float4 b0v = *(const float4*)(b0 + colBase + (tx << 2));
    const float4 b1v = *(const float4*)(b1 + colBase + (tx << 2));

#pragma unroll 1
    for (int t = 0; t < T_; t++) {
        const int pv = t & 1;
        const int cu = pv ^ 1;
        const float* H0p = g_H0 + (size_t)pv * (B_ * U_);
        float* H0c = g_H0 + (size_t)cu * (B_ * U_);
        const float* H1p = g_H1 + (size_t)pv * (B_ * U_);
        float* H1c = g_H1 + (size_t)cu * (B_ * U_);

        // --- layer 0: acc = EW0[inputs[b,t]] + b0; acc += H0p @ U0 ---
        float acc[8][4];
#pragma unroll
        for (int i = 0; i < 8; i++) {
            int r = rowBase + (ty << 3) + i;
            int idx = __ldg(inputs + r * T_ + t);
            float4 p = ld4_ro(g_EW0 + (size_t)idx * U_ + colBase + (tx << 2));
            acc[i][0] = p.x + b0v.x;
            acc[i][1] = p.y + b0v.y;
            acc[i][2] = p.z + b0v.z;
            acc[i][3] = p.w + b0v.w;
        }
        gemm_tile<true>(H0p, U_, B_ - 1, U0, U_, U_, rowBase, colBase, AsS, BsS, acc, tid);
#pragma unroll
        for (int i = 0; i < 8; i++) {
            int r = rowBase + (ty << 3) + i;
            float4 o = make_float4(tanhf(acc[i][0]), tanhf(acc[i][1]),
                                   tanhf(acc[i][2]), tanhf(acc[i][3]));
            __stcg((float4*)(H0c + (size_t)r * U_ + colBase + (tx << 2)), o);
        }
        grid_sync();

        // --- layer 1: acc = b1; acc += H0c @ W1; acc += H1p @ U1 ---
#pragma unroll
        for (int i = 0; i < 8; i++) {
            acc[i][0] = b1v.x;
            acc[i][1] = b1v.y;
            acc[i][2] = b1v.z;
            acc[i][3] = b1v.w;
        }
        gemm_tile<true>(H0c, U_, B_ - 1, W1, U_, U_, rowBase, colBase, AsS, BsS, acc, tid);
        gemm_tile<true>(H1p, U_, B_ - 1, U1, U_, U_, rowBase, colBase, AsS, BsS, acc, tid);
#pragma unroll
        for (int i = 0; i < 8; i++) {
            int r = rowBase + (ty << 3) + i;
            float4 o = make_float4(tanhf(acc[i][0]), tanhf(acc[i][1]),
                                   tanhf(acc[i][2]), tanhf(acc[i][3]));
            __stcg((float4*)(H1c + (size_t)r * U_ + colBase + (tx << 2)), o);
        }
        grid_sync();
    }
}

// ---------------------------------------------------------------------------
// Phase 3: out[b] = sigmoid(H1_final[b,:] . Wout + bout)
// Final state is parity 0 (T=256 even). One CTA per batch row.
// ---------------------------------------------------------------------------
__global__ void __launch_bounds__(128) k_out(const float* __restrict__ Wout,
                                             const float* __restrict__ bout,
                                             float* __restrict__ out) {
    const int b = blockIdx.x;
    const int tid = threadIdx.x;
    __shared__ float red[128];
    const float* h = g_H1 + (size_t)b * U_;  // parity-0 buffer
    float s = 0.f;
    for (int u = tid; u < U_; u += 128) s += h[u] * Wout[u];
    red[tid] = s;
    __syncthreads();
    for (int o = 64; o > 0; o >>= 1) {
        if (tid < o) red[tid] += red[tid + o];
        __syncthreads();
    }
    if (tid == 0) {
        float z = red[0] + bout[0];
        out[b] = 1.f / (1.f + expf(-z));
    }
}

// ---------------------------------------------------------------------------
extern "C" void kernel_launch(void* const* d_in, const int* in_sizes, int n_in,
                              void* d_out, int out_size) {
    const int* inputs = (const int*)d_in[0];
    const float* emb = (const float*)d_in[1];
    const float* W0 = (const float*)d_in[2];
    const float* U0 = (const float*)d_in[3];
    const float* b0 = (const float*)d_in[4];
    const float* W1 = (const float*)d_in[5];
    const float* U1 = (const float*)d_in[6];
    const float* b1 = (const float*)d_in[7];
    const float* Wout = (const float*)d_in[8];
    const float* bout = (const float*)d_in[9];
    float* out = (float*)d_out;

    dim3 g1((V_ + BM - 1) / BM, U_ / BN);  // 391 x 16
    k_ew0<<<g1, 256>>>(emb, W0);
    k_rnn_persistent<<<NBLK, 256>>>(inputs, U0, b0, W1, U1, b1);
    k_out<<<B_, 128>>>(Wout, bout, out);
}

// round 2
// speedup vs baseline: 1.0015x; 1.0015x over previous
#include <cuda_runtime.h>
#include <cuda_bf16.h>

// Problem constants
#define B_ 1024
#define T_ 256
#define V_ 50000
#define E_ 512
#define U_ 1024

// GEMM tiling
#define BM 128
#define BN 64
#define BK 16
#define ASTRIDE (BM + 4)   // 132: keeps 16B alignment for LDS.128, reduces STS conflicts
#define NBLK 128           // persistent grid: (1024/BM) * (1024/BN) = 8*16

// Scratch (device globals: allocation-free per harness rules)
__device__ float g_EW0[(size_t)V_ * U_];       // 204.8 MB: emb @ W0, gathered per step
__device__ float g_H0[2 * B_ * U_];            // ping-pong hidden state layer 0
__device__ float g_H1[2 * B_ * U_];            // ping-pong hidden state layer 1
__device__ unsigned g_bar_count = 0;
__device__ volatile unsigned g_bar_gen = 0;

// ---------------------------------------------------------------------------
// Grid-wide barrier (128 resident CTAs). Release via gen counter; count reset
// by releaser. threadfence publishes H writes (stores are .cg -> L2 anyway).
// ---------------------------------------------------------------------------
__device__ __forceinline__ void grid_sync() {
    __syncthreads();
    if (threadIdx.x == 0) {
        __threadfence();
        unsigned g = g_bar_gen;
        unsigned a = atomicAdd(&g_bar_count, 1);
        if (a == NBLK - 1) {
            g_bar_count = 0;
            __threadfence();
            g_bar_gen = g + 1;
        } else {
            while (g_bar_gen == g) { __nanosleep(32); }
        }
        __threadfence();
    }
    __syncthreads();
}

// ---------------------------------------------------------------------------
// Shared SGEMM mainloop: C_tile(128x64) += A[rows,K] * B[K,cols]
// 256 threads, 8x4 per thread, double-buffered smem.
// ACG=true -> A loaded with .cg (mutable H state; L1 is stale across SMs).
// ---------------------------------------------------------------------------
__device__ __forceinline__ float4 ld4_cg(const float* p) { return __ldcg((const float4*)p); }
__device__ __forceinline__ float4 ld4_ro(const float* p) { return __ldg((const float4*)p); }

template <bool ACG>
__device__ __forceinline__ void gt_loadA(float4 aR[2], const float* A, int lda,
                                         int rowBase, int kBase, int maxRow, int tid) {
#pragma unroll
    for (int j = 0; j < 2; j++) {
        int i = tid + (j << 8);
        int arow = i >> 2;
        int acol = (i & 3) << 2;
        int r = rowBase + arow;
        if (r > maxRow) r = maxRow;
        const float* p = A + (size_t)r * lda + kBase + acol;
        aR[j] = ACG ? ld4_cg(p) : ld4_ro(p);
    }
}

__device__ __forceinline__ void gt_storeA(const float4 aR[2], float* AsBuf, int tid) {
#pragma unroll
    for (int j = 0; j < 2; j++) {
        int i = tid + (j << 8);
        int arow = i >> 2;
        int acol = (i & 3) << 2;
        AsBuf[(acol + 0) * ASTRIDE + arow] = aR[j].x;
        AsBuf[(acol + 1) * ASTRIDE + arow] = aR[j].y;
        AsBuf[(acol + 2) * ASTRIDE + arow] = aR[j].z;
        AsBuf[(acol + 3) * ASTRIDE + arow] = aR[j].w;
    }
}

__device__ __forceinline__ void gt_loadB(float4& bR, const float* Bm, int ldb,
                                         int colBase, int kBase, int tid) {
    int brow = tid >> 4;
    int bcol = (tid & 15) << 2;
    bR = ld4_ro(Bm + (size_t)(kBase + brow) * ldb + colBase + bcol);
}

__device__ __forceinline__ void gt_storeB(const float4 bR, float* BsBuf, int tid) {
    int brow = tid >> 4;
    int bcol = (tid & 15) << 2;
    *(float4*)(BsBuf + brow * BN + bcol) = bR;
}

template <bool ACG>
__device__ __forceinline__ void gemm_tile(const float* __restrict__ A, int lda, int maxRow,
                                          const float* __restrict__ Bm, int ldb, int K,
                                          int rowBase, int colBase,
                                          float* AsS, float* BsS,
                                          float acc[8][4], int tid) {
    const int ABUF = BK * ASTRIDE;
    const int BBUF = BK * BN;
    const int tx = tid & 15;
    const int ty = tid >> 4;

    float4 aR[2];
    float4 bR;
    gt_loadA<ACG>(aR, A, lda, rowBase, 0, maxRow, tid);
    gt_loadB(bR, Bm, ldb, colBase, 0, tid);
    gt_storeA(aR, AsS, tid);
    gt_storeB(bR, BsS, tid);
    __syncthreads();

    const int nC = K >> 4;
#pragma unroll 2
    for (int c = 0; c < nC; c++) {
        const int cur = c & 1;
        if (c + 1 < nC) {
            gt_loadA<ACG>(aR, A, lda, rowBase, (c + 1) << 4, maxRow, tid);
            gt_loadB(bR, Bm, ldb, colBase, (c + 1) << 4, tid);
        }
        const float* As = AsS + cur * ABUF;
        const float* Bs = BsS + cur * BBUF;
#pragma unroll 8
        for (int k = 0; k < BK; k++) {
            float4 a0 = *(const float4*)(As + k * ASTRIDE + (ty << 3));
            float4 a1 = *(const float4*)(As + k * ASTRIDE + (ty << 3) + 4);
            float4 bv = *(const float4*)(Bs + k * BN + (tx << 2));
            float av[8] = {a0.x, a0.y, a0.z, a0.w, a1.x, a1.y, a1.z, a1.w};
            float bw[4] = {bv.x, bv.y, bv.z, bv.w};
#pragma unroll
            for (int i = 0; i < 8; i++)
#pragma unroll
                for (int j = 0; j < 4; j++)
                    acc[i][j] = fmaf(av[i], bw[j], acc[i][j]);
        }
        if (c + 1 < nC) {
            gt_storeA(aR, AsS + (cur ^ 1) * ABUF, tid);
            gt_storeB(bR, BsS + (cur ^ 1) * BBUF, tid);
        }
        __syncthreads();
    }
}

// ---------------------------------------------------------------------------
// Phase 1: EW0[V,U] = emb[V,E] @ W0[E,U]   (52 GF, embarrassingly parallel)
// ---------------------------------------------------------------------------
__global__ void __launch_bounds__(256) k_ew0(const float* __restrict__ emb,
                                             const float* __restrict__ W0) {
    __shared__ float AsS[2 * BK * ASTRIDE];
    __shared__ float BsS[2 * BK * BN];
    const int tid = threadIdx.x;
    const int tx = tid & 15;
    const int ty = tid >> 4;
    const int rowBase = blockIdx.x << 7;
    const int colBase = blockIdx.y << 6;

    float acc[8][4];
#pragma unroll
    for (int i = 0; i < 8; i++)
#pragma unroll
        for (int j = 0; j < 4; j++) acc[i][j] = 0.f;

    gemm_tile<false>(emb, E_, V_ - 1, W0, U_, E_, rowBase, colBase, AsS, BsS, acc, tid);

#pragma unroll
    for (int i = 0; i < 8; i++) {
        int r = rowBase + (ty << 3) + i;
        if (r < V_) {
            float4 o = make_float4(acc[i][0], acc[i][1], acc[i][2], acc[i][3]);
            *(float4*)(g_EW0 + (size_t)r * U_ + colBase + (tx << 2)) = o;
        }
    }
}

// ---------------------------------------------------------------------------
// Phase 2: persistent RNN. 128 CTAs; each owns one 128x64 tile of H.
// Per step:  H0c = tanh(EW0[idx] + H0p@U0 + b0)   -> sync
//            H1c = tanh(H0c@W1 + H1p@U1 + b1)     -> sync
// ---------------------------------------------------------------------------
__global__ void __launch_bounds__(256, 1) k_rnn_persistent(
    const int* __restrict__ inputs,
    const float* __restrict__ U0, const float* __restrict__ b0,
    const float* __restrict__ W1, const float* __restrict__ U1,
    const float* __restrict__ b1) {
    __shared__ float AsS[2 * BK * ASTRIDE];
    __shared__ float BsS[2 * BK * BN];
    const int tid = threadIdx.x;
    const int bid = blockIdx.x;
    const int tx = tid & 15;
    const int ty = tid >> 4;
    const int rowBase = (bid >> 4) << 7;  // 8 row tiles of 128
    const int colBase = (bid & 15) << 6;  // 16 col tiles of 64

    // Zero-init parity-0 state buffers (read at t=0). .cg stores -> L2 visible.
    {
        float4 z = make_float4(0.f, 0.f, 0.f, 0.f);
        float4* h0 = (float4*)g_H0;
        float4* h1 = (float4*)g_H1;
        for (int i = (bid << 8) + tid; i < (B_ * U_ / 4); i += NBLK * 256) {
            __stcg(h0 + i, z);
            __stcg(h1 + i, z);
        }
    }
    grid_sync();

    const float4 b0v = *(const float4*)(b0 + colBase + (tx << 2));
    const float4 b1v = *(const float4*)(b1 + colBase + (tx << 2));

#pragma unroll 1
    for (int t = 0; t < T_; t++) {
        const int pv = t & 1;
        const int cu = pv ^ 1;
        const float* H0p = g_H0 + (size_t)pv * (B_ * U_);
        float* H0c = g_H0 + (size_t)cu * (B_ * U_);
        const float* H1p = g_H1 + (size_t)pv * (B_ * U_);
        float* H1c = g_H1 + (size_t)cu * (B_ * U_);

        // --- layer 0: acc = EW0[inputs[b,t]] + b0; acc += H0p @ U0 ---
        float acc[8][4];
#pragma unroll
        for (int i = 0; i < 8; i++) {
            int r = rowBase + (ty << 3) + i;
            int idx = __ldg(inputs + r * T_ + t);
            float4 p = ld4_ro(g_EW0 + (size_t)idx * U_ + colBase + (tx << 2));
            acc[i][0] = p.x + b0v.x;
            acc[i][1] = p.y + b0v.y;
            acc[i][2] = p.z + b0v.z;
            acc[i][3] = p.w + b0v.w;
        }
        gemm_tile<true>(H0p, U_, B_ - 1, U0, U_, U_, rowBase, colBase, AsS, BsS, acc, tid);
#pragma unroll
        for (int i = 0; i < 8; i++) {
            int r = rowBase + (ty << 3) + i;
            float4 o = make_float4(tanhf(acc[i][0]), tanhf(acc[i][1]),
                                   tanhf(acc[i][2]), tanhf(acc[i][3]));
            __stcg((float4*)(H0c + (size_t)r * U_ + colBase + (tx << 2)), o);
        }
        grid_sync();

        // --- layer 1: acc = b1; acc += H0c @ W1; acc += H1p @ U1 ---
#pragma unroll
        for (int i = 0; i < 8; i++) {
            acc[i][0] = b1v.x;
            acc[i][1] = b1v.y;
            acc[i][2] = b1v.z;
            acc[i][3] = b1v.w;
        }
        gemm_tile<true>(H0c, U_, B_ - 1, W1, U_, U_, rowBase, colBase, AsS, BsS, acc, tid);
        gemm_tile<true>(H1p, U_, B_ - 1, U1, U_, U_, rowBase, colBase, AsS, BsS, acc, tid);
#pragma unroll
        for (int i = 0; i < 8; i++) {
            int r = rowBase + (ty << 3) + i;
            float4 o = make_float4(tanhf(acc[i][0]), tanhf(acc[i][1]),
                                   tanhf(acc[i][2]), tanhf(acc[i][3]));
            __stcg((float4*)(H1c + (size_t)r * U_ + colBase + (tx << 2)), o);
        }
        grid_sync();
    }
}

// ---------------------------------------------------------------------------
// Phase 3: out[b] = sigmoid(H1_final[b,:] . Wout + bout)
// Final state is parity 0 (T=256 even). One CTA per batch row.
// ---------------------------------------------------------------------------
__global__ void __launch_bounds__(128) k_out(const float* __restrict__ Wout,
                                             const float* __restrict__ bout,
                                             float* __restrict__ out) {
    const int b = blockIdx.x;
    const int tid = threadIdx.x;
    __shared__ float red[128];
    const float* h = g_H1 + (size_t)b * U_;  // parity-0 buffer
    float s = 0.f;
    for (int u = tid; u < U_; u += 128) s += h[u] * Wout[u];
    red[tid] = s;
    __syncthreads();
    for (int o = 64; o > 0; o >>= 1) {
        if (tid < o) red[tid] += red[tid + o];
        __syncthreads();
    }
    if (tid == 0) {
        float z = red[0] + bout[0];
        out[b] = 1.f / (1.f + expf(-z));
    }
}

// ---------------------------------------------------------------------------
extern "C" void kernel_launch(void* const* d_in, const int* in_sizes, int n_in,
                              void* d_out, int out_size) {
    const int* inputs = (const int*)d_in[0];
    const float* emb = (const float*)d_in[1];
    const float* W0 = (const float*)d_in[2];
    const float* U0 = (const float*)d_in[3];
    const float* b0 = (const float*)d_in[4];
    const float* W1 = (const float*)d_in[5];
    const float* U1 = (const float*)d_in[6];
    const float* b1 = (const float*)d_in[7];
    const float* Wout = (const float*)d_in[8];
    const float* bout = (const float*)d_in[9];
    float* out = (float*)d_out;

    dim3 g1((V_ + BM - 1) / BM, U_ / BN);  // 391 x 16
    k_ew0<<<g1, 256>>>(emb, W0);
    k_rnn_persistent<<<NBLK, 256>>>(inputs, U0, b0, W1, U1, b1);
    k_out<<<B_, 128>>>(Wout, bout, out);
}

// round 3
// speedup vs baseline: 1.0017x; 1.0002x over previous
#include <cuda_runtime.h>
#include <cuda_bf16.h>

// Problem constants
#define B_ 1024
#define T_ 256
#define V_ 50000
#define E_ 512
#define U_ 1024

// GEMM tiling
#define BM 128
#define BN 64
#define BK 16
#define ASTRIDE (BM + 4)   // 132: keeps 16B alignment for LDS.128, reduces STS conflicts
#define NBLK 128           // persistent grid: (1024/BM) * (1024/BN) = 8*16

// Scratch (device globals: allocation-free per harness rules)
__device__ float g_EW0[(size_t)V_ * U_];       // 204.8 MB: emb @ W0, gathered per step
__device__ float g_H0[2 * B_ * U_];            // ping-pong hidden state layer 0
__device__ float g_H1[2 * B_ * U_];            // ping-pong hidden state layer 1
__device__ unsigned g_bar_count = 0;
__device__ volatile unsigned g_bar_gen = 0;

// ---------------------------------------------------------------------------
// Grid-wide barrier (128 resident CTAs). Release via gen counter; count reset
// by releaser. threadfence publishes H writes (stores are .cg -> L2 anyway).
// ---------------------------------------------------------------------------
__device__ __forceinline__ void grid_sync() {
    __syncthreads();
    if (threadIdx.x == 0) {
        __threadfence();
        unsigned g = g_bar_gen;
        unsigned a = atomicAdd(&g_bar_count, 1);
        if (a == NBLK - 1) {
            g_bar_count = 0;
            __threadfence();
            g_bar_gen = g + 1;
        } else {
            while (g_bar_gen == g) { __nanosleep(32); }
        }
        __threadfence();
    }
    __syncthreads();
}

// ---------------------------------------------------------------------------
// Shared SGEMM mainloop: C_tile(128x64) += A[rows,K] * B[K,cols]
// 256 threads, 8x4 per thread, double-buffered smem.
// ACG=true -> A loaded with .cg (mutable H state; L1 is stale across SMs).
// ---------------------------------------------------------------------------
__device__ __forceinline__ float4 ld4_cg(const float* p) { return __ldcg((const float4*)p); }
__device__ __forceinline__ float4 ld4_ro(const float* p) { return __ldg((const float4*)p); }

template <bool ACG>
__device__ __forceinline__ void gt_loadA(float4 aR[2], const float* A, int lda,
                                         int rowBase, int kBase, int maxRow, int tid) {
#pragma unroll
    for (int j = 0; j < 2; j++) {
        int i = tid + (j << 8);
        int arow = i >> 2;
        int acol = (i & 3) << 2;
        int r = rowBase + arow;
        if (r > maxRow) r = maxRow;
        const float* p = A + (size_t)r * lda + kBase + acol;
        aR[j] = ACG ? ld4_cg(p) : ld4_ro(p);
    }
}

__device__ __forceinline__ void gt_storeA(const float4 aR[2], float* AsBuf, int tid) {
#pragma unroll
    for (int j = 0; j < 2; j++) {
        int i = tid + (j << 8);
        int arow = i >> 2;
        int acol = (i & 3) << 2;
        AsBuf[(acol + 0) * ASTRIDE + arow] = aR[j].x;
        AsBuf[(acol + 1) * ASTRIDE + arow] = aR[j].y;
        AsBuf[(acol + 2) * ASTRIDE + arow] = aR[j].z;
        AsBuf[(acol + 3) * ASTRIDE + arow] = aR[j].w;
    }
}

__device__ __forceinline__ void gt_loadB(float4& bR, const float* Bm, int ldb,
                                         int colBase, int kBase, int tid) {
    int brow = tid >> 4;
    int bcol = (tid & 15) << 2;
    bR = ld4_ro(Bm + (size_t)(kBase + brow) * ldb + colBase + bcol);
}

__device__ __forceinline__ void gt_storeB(const float4 bR, float* BsBuf, int tid) {
    int brow = tid >> 4;
    int bcol = (tid & 15) << 2;
    *(float4*)(BsBuf + brow * BN + bcol) = bR;
}

template <bool ACG>
__device__ __forceinline__ void gemm_tile(const float* __restrict__ A, int lda, int maxRow,
                                          const float* __restrict__ Bm, int ldb, int K,
                                          int rowBase, int colBase,
                                          float* AsS, float* BsS,
                                          float acc[8][4], int tid) {
    const int ABUF = BK * ASTRIDE;
    const int BBUF = BK * BN;
    const int tx = tid & 15;
    const int ty = tid >> 4;

    float4 aR[2];
    float4 bR;
    gt_loadA<ACG>(aR, A, lda, rowBase, 0, maxRow, tid);
    gt_loadB(bR, Bm, ldb, colBase, 0, tid);
    gt_storeA(aR, AsS, tid);
    gt_storeB(bR, BsS, tid);
    __syncthreads();

    const int nC = K >> 4;
#pragma unroll 2
    for (int c = 0; c < nC; c++) {
        const int cur = c & 1;
        if (c + 1 < nC) {
            gt_loadA<ACG>(aR, A, lda, rowBase, (c + 1) << 4, maxRow, tid);
            gt_loadB(bR, Bm, ldb, colBase, (c + 1) << 4, tid);
        }
        const float* As = AsS + cur * ABUF;
        const float* Bs = BsS + cur * BBUF;
#pragma unroll 8
        for (int k = 0; k < BK; k++) {
            float4 a0 = *(const float4*)(As + k * ASTRIDE + (ty << 3));
            float4 a1 = *(const float4*)(As + k * ASTRIDE + (ty << 3) + 4);
            float4 bv = *(const float4*)(Bs + k * BN + (tx << 2));
            float av[8] = {a0.x, a0.y, a0.z, a0.w, a1.x, a1.y, a1.z, a1.w};
            float bw[4] = {bv.x, bv.y, bv.z, bv.w};
#pragma unroll
            for (int i = 0; i < 8; i++)
#pragma unroll
                for (int j = 0; j < 4; j++)
                    acc[i][j] = fmaf(av[i], bw[j], acc[i][j]);
        }
        if (c + 1 < nC) {
            gt_storeA(aR, AsS + (cur ^ 1) * ABUF, tid);
            gt_storeB(bR, BsS + (cur ^ 1) * BBUF, tid);
        }
        __syncthreads();
    }
}

// ---------------------------------------------------------------------------
// Phase 1: EW0[V,U] = emb[V,E] @ W0[E,U]   (52 GF, embarrassingly parallel)
// ---------------------------------------------------------------------------
__global__ void __launch_bounds__(256) k_ew0(const float* __restrict__ emb,
                                             const float* __restrict__ W0) {
    __shared__ float AsS[2 * BK * ASTRIDE];
    __shared__ float BsS[2 * BK * BN];
    const int tid = threadIdx.x;
    const int tx = tid & 15;
    const int ty = tid >> 4;
    const int rowBase = blockIdx.x << 7;
    const int colBase = blockIdx.y << 6;

    float acc[8][4];
#pragma unroll
    for (int i = 0; i < 8; i++)
#pragma unroll
        for (int j = 0; j < 4; j++) acc[i][j] = 0.f;

    gemm_tile<false>(emb, E_, V_ - 1, W0, U_, E_, rowBase, colBase, AsS, BsS, acc, tid);

#pragma unroll
    for (int i = 0; i < 8; i++) {
        int r = rowBase + (ty << 3) + i;
        if (r < V_) {
            float4 o = make_float4(acc[i][0], acc[i][1], acc[i][2], acc[i][3]);
            *(float4*)(g_EW0 + (size_t)r * U_ + colBase + (tx << 2)) = o;
        }
    }
}

// ---------------------------------------------------------------------------
// Phase 2: persistent RNN. 128 CTAs; each owns one 128x64 tile of H.
// Per step:  H0c = tanh(EW0[idx] + H0p@U0 + b0)   -> sync
//            H1c = tanh(H0c@W1 + H1p@U1 + b1)     -> sync
// ---------------------------------------------------------------------------
__global__ void __launch_bounds__(256, 1) k_rnn_persistent(
    const int* __restrict__ inputs,
    const float* __restrict__ U0, const float* __restrict__ b0,
    const float* __restrict__ W1, const float* __restrict__ U1,
    const float* __restrict__ b1) {
    __shared__ float AsS[2 * BK * ASTRIDE];
    __shared__ float BsS[2 * BK * BN];
    const int tid = threadIdx.x;
    const int bid = blockIdx.x;
    const int tx = tid & 15;
    const int ty = tid >> 4;
    const int rowBase = (bid >> 4) << 7;  // 8 row tiles of 128
    const int colBase = (bid & 15) << 6;  // 16 col tiles of 64

    // Zero-init parity-0 state buffers (read at t=0). .cg stores -> L2 visible.
    {
        float4 z = make_float4(0.f, 0.f, 0.f, 0.f);
        float4* h0 = (float4*)g_H0;
        float4* h1 = (float4*)g_H1;
        for (int i = (bid << 8) + tid; i < (B_ * U_ / 4); i += NBLK * 256) {
            __stcg(h0 + i, z);
            __stcg(h1 + i, z);
        }
    }
    grid_sync();

    const float4 b0v = *(const float4*)(b0 + colBase + (tx << 2));
    const float4 b1v = *(const float4*)(b1 + colBase + (tx << 2));

#pragma unroll 1
    for (int t = 0; t < T_; t++) {
        const int pv = t & 1;
        const int cu = pv ^ 1;
        const float* H0p = g_H0 + (size_t)pv * (B_ * U_);
        float* H0c = g_H0 + (size_t)cu * (B_ * U_);
        const float* H1p = g_H1 + (size_t)pv * (B_ * U_);
        float* H1c = g_H1 + (size_t)cu * (B_ * U_);

        // --- layer 0: acc = EW0[inputs[b,t]] + b0; acc += H0p @ U0 ---
        float acc[8][4];
#pragma unroll
        for (int i = 0; i < 8; i++) {
            int r = rowBase + (ty << 3) + i;
            int idx = __ldg(inputs + r * T_ + t);
            float4 p = ld4_ro(g_EW0 + (size_t)idx * U_ + colBase + (tx << 2));
            acc[i][0] = p.x + b0v.x;
            acc[i][1] = p.y + b0v.y;
            acc[i][2] = p.z + b0v.z;
            acc[i][3] = p.w + b0v.w;
        }
        gemm_tile<true>(H0p, U_, B_ - 1, U0, U_, U_, rowBase, colBase, AsS, BsS, acc, tid);
#pragma unroll
        for (int i = 0; i < 8; i++) {
            int r = rowBase + (ty << 3) + i;
            float4 o = make_float4(tanhf(acc[i][0]), tanhf(acc[i][1]),
                                   tanhf(acc[i][2]), tanhf(acc[i][3]));
            __stcg((float4*)(H0c + (size_t)r * U_ + colBase + (tx << 2)), o);
        }
        grid_sync();

        // --- layer 1: acc = b1; acc += H0c @ W1; acc += H1p @ U1 ---
#pragma unroll
        for (int i = 0; i < 8; i++) {
            acc[i][0] = b1v.x;
            acc[i][1] = b1v.y;
            acc[i][2] = b1v.z;
            acc[i][3] = b1v.w;
        }
        gemm_tile<true>(H0c, U_, B_ - 1, W1, U_, U_, rowBase, colBase, AsS, BsS, acc, tid);
        gemm_tile<true>(H1p, U_, B_ - 1, U1, U_, U_, rowBase, colBase, AsS, BsS, acc, tid);
#pragma unroll
        for (int i = 0; i < 8; i++) {
            int r = rowBase + (ty << 3) + i;
            float4 o = make_float4(tanhf(acc[i][0]), tanhf(acc[i][1]),
                                   tanhf(acc[i][2]), tanhf(acc[i][3]));
            __stcg((float4*)(H1c + (size_t)r * U_ + colBase + (tx << 2)), o);
        }
        grid_sync();
    }
}

// ---------------------------------------------------------------------------
// Phase 3: out[b] = sigmoid(H1_final[b,:] . Wout + bout)
// Final state is parity 0 (T=256 even). One CTA per batch row.
// ---------------------------------------------------------------------------
__global__ void __launch_bounds__(128) k_out(const float* __restrict__ Wout,
                                             const float* __restrict__ bout,
                                             float* __restrict__ out) {
    const int b = blockIdx.x;
    const int tid = threadIdx.x;
    __shared__ float red[128];
    const float* h = g_H1 + (size_t)b * U_;  // parity-0 buffer
    float s = 0.f;
    for (int u = tid; u < U_; u += 128) s += h[u] * Wout[u];
    red[tid] = s;
    __syncthreads();
    for (int o = 64; o > 0; o >>= 1) {
        if (tid < o) red[tid] += red[tid + o];
        __syncthreads();
    }
    if (tid == 0) {
        float z = red[0] + bout[0];
        out[b] = 1.f / (1.f + expf(-z));
    }
}

// ---------------------------------------------------------------------------
extern "C" void kernel_launch(void* const* d_in, const int* in_sizes, int n_in,
                              void* d_out, int out_size) {
    const int* inputs = (const int*)d_in[0];
    const float* emb = (const float*)d_in[1];
    const float* W0 = (const float*)d_in[2];
    const float* U0 = (const float*)d_in[3];
    const float* b0 = (const float*)d_in[4];
    const float* W1 = (const float*)d_in[5];
    const float* U1 = (const float*)d_in[6];
    const float* b1 = (const float*)d_in[7];
    const float* Wout = (const float*)d_in[8];
    const float* bout = (const float*)d_in[9];
    float* out = (float*)d_out;

    dim3 g1((V_ + BM - 1) / BM, U_ / BN);  // 391 x 16
    k_ew0<<<g1, 256>>>(emb, W0);
    k_rnn_persistent<<<NBLK, 256>>>(inputs, U0, b0, W1, U1, b1);
    k_out<<<B_, 128>>>(Wout, bout, out);
}